// round 1
// baseline (speedup 1.0000x reference)
#include <cuda_runtime.h>
#include <math.h>

#define N_NODES 8192
#define E_EDGES 262144
#define IN_CH_  128
#define MP_CH   512
#define HID_    256
#define KCL     10
#define EPSF    0.001f
#define DELTAF  0.311f
#define TV_COEFF 0.785f
#define BAL_COEFF 0.514f

// ---------------- scratch (device globals; no allocation allowed) ----------------
__device__ float    g_bufA[N_NODES * MP_CH];
__device__ float    g_bufB[N_NODES * MP_CH];
__device__ float    g_hid [N_NODES * HID_];
__device__ float    g_s   [N_NODES * KCL];
__device__ unsigned g_bitmap[(N_NODES * (size_t)N_NODES) / 32];   // 8 MB
__device__ int      g_counts[N_NODES];
__device__ int      g_rowptr[N_NODES + 1];
__device__ int      g_offs  [N_NODES];
__device__ int      g_perm  [E_EDGES];
__device__ int      g_nedges;
__device__ double   g_tv_part[1024];
__device__ double   g_asym_part[320];
__device__ float    g_quant[KCL];

// ---------------- clear ----------------
__global__ void k_clear() {
    int i = blockIdx.x * blockDim.x + threadIdx.x;
    const int total = (N_NODES * N_NODES) / 32;
    if (i < total) g_bitmap[i] = 0u;
    if (i < N_NODES) { g_counts[i] = 0; g_offs[i] = 0; }
    if (i == 0) g_nedges = 0;
}

// ---------------- CSR build (by dst) ----------------
__global__ void k_hist(const int* __restrict__ dst) {
    int e = blockIdx.x * blockDim.x + threadIdx.x;
    if (e < E_EDGES) atomicAdd(&g_counts[dst[e]], 1);
}

__global__ void k_scan() {   // single block, 1024 threads, 8 elems each
    __shared__ int tsum[1024];
    int tid = threadIdx.x;
    int base = tid * 8;
    int local[8];
    int s = 0;
    #pragma unroll
    for (int i = 0; i < 8; i++) { local[i] = s; s += g_counts[base + i]; }
    tsum[tid] = s;
    __syncthreads();
    for (int off = 1; off < 1024; off <<= 1) {
        int v = 0;
        if (tid >= off) v = tsum[tid - off];
        __syncthreads();
        if (tid >= off) tsum[tid] += v;
        __syncthreads();
    }
    int prefix = tsum[tid] - s;  // exclusive chunk prefix
    #pragma unroll
    for (int i = 0; i < 8; i++) g_rowptr[base + i] = prefix + local[i];
    if (tid == 1023) g_rowptr[N_NODES] = tsum[1023];
}

__global__ void k_scatter(const int* __restrict__ dst) {
    int e = blockIdx.x * blockDim.x + threadIdx.x;
    if (e < E_EDGES) {
        int d = dst[e];
        int pos = g_rowptr[d] + atomicAdd(&g_offs[d], 1);
        g_perm[pos] = e;
    }
}

// ---------------- SGEMM: C[M x Nn] = A[M x K] @ B[K x Nn] (+bias)(+relu) --------
// 128x128 block tile, BK=8, 256 threads, 8x8 per thread.
__global__ __launch_bounds__(256) void k_sgemm(
    const float* __restrict__ A, const float* __restrict__ B,
    const float* __restrict__ bias, float* __restrict__ C,
    int Kdim, int Nn, int relu)
{
    __shared__ float As[8][136];
    __shared__ float Bs[8][128];
    int tid = threadIdx.x;
    int tx = tid & 15, ty = tid >> 4;
    int aRow = tid >> 1;
    int aCol = (tid & 1) << 2;
    int bRow = tid >> 5;
    int bCol = (tid & 31) << 2;
    const float* Ap = A + (blockIdx.y * 128) * (size_t)Kdim;
    const float* Bp = B + blockIdx.x * 128;
    float acc[8][8];
    #pragma unroll
    for (int i = 0; i < 8; i++)
        #pragma unroll
        for (int j = 0; j < 8; j++) acc[i][j] = 0.f;

    for (int k0 = 0; k0 < Kdim; k0 += 8) {
        float4 a4 = *(const float4*)(Ap + (size_t)aRow * Kdim + k0 + aCol);
        As[aCol + 0][aRow] = a4.x;
        As[aCol + 1][aRow] = a4.y;
        As[aCol + 2][aRow] = a4.z;
        As[aCol + 3][aRow] = a4.w;
        *(float4*)(&Bs[bRow][bCol]) = *(const float4*)(Bp + (size_t)(k0 + bRow) * Nn + bCol);
        __syncthreads();
        #pragma unroll
        for (int kk = 0; kk < 8; kk++) {
            float af[8], bf[8];
            #pragma unroll
            for (int i = 0; i < 8; i++) af[i] = As[kk][ty * 8 + i];
            #pragma unroll
            for (int j = 0; j < 8; j++) bf[j] = Bs[kk][tx * 8 + j];
            #pragma unroll
            for (int i = 0; i < 8; i++)
                #pragma unroll
                for (int j = 0; j < 8; j++) acc[i][j] = fmaf(af[i], bf[j], acc[i][j]);
        }
        __syncthreads();
    }
    int row0 = blockIdx.y * 128 + ty * 8;
    int col0 = blockIdx.x * 128 + tx * 8;
    #pragma unroll
    for (int i = 0; i < 8; i++)
        #pragma unroll
        for (int j = 0; j < 8; j++) {
            float v = acc[i][j];
            if (bias) v += bias[col0 + j];
            if (relu) v = fmaxf(v, 0.f);
            C[(size_t)(row0 + i) * Nn + col0 + j] = v;
        }
}

// ---------------- GTVConv aggregate + elu (warp per dst node) ----------------
__global__ __launch_bounds__(256) void k_conv(
    const float* __restrict__ h, const float* __restrict__ bias,
    const int* __restrict__ src, const float* __restrict__ ew,
    float* __restrict__ out)
{
    int warp = (blockIdx.x * blockDim.x + threadIdx.x) >> 5;
    int lane = threadIdx.x & 31;
    if (warp >= N_NODES) return;
    const float* hdp = h + (size_t)warp * MP_CH;
    float hd[16], acc[16];
    #pragma unroll
    for (int j = 0; j < 16; j++) { hd[j] = hdp[lane + 32 * j]; acc[j] = 0.f; }
    float deg = 0.f;
    int p0 = g_rowptr[warp], p1 = g_rowptr[warp + 1];
    for (int p = p0; p < p1; p++) {
        int e = g_perm[p];
        int s = src[e];
        float w = ew[e];
        const float* hs = h + (size_t)s * MP_CH;
        float v[16];
        float d = 0.f;
        #pragma unroll
        for (int j = 0; j < 16; j++) { v[j] = hs[lane + 32 * j]; d += fabsf(v[j] - hd[j]); }
        #pragma unroll
        for (int o = 16; o > 0; o >>= 1) d += __shfl_xor_sync(0xffffffffu, d, o);
        float gamma = w / fmaxf(d, EPSF);
        deg += gamma;
        #pragma unroll
        for (int j = 0; j < 16; j++) acc[j] = fmaf(gamma, v[j], acc[j]);
    }
    float* op = out + (size_t)warp * MP_CH;
    #pragma unroll
    for (int j = 0; j < 16; j++) {
        int c = lane + 32 * j;
        float o = hd[j] - DELTAF * (deg * hd[j] - acc[j]) + bias[c];
        op[c] = (o > 0.f) ? o : expm1f(o);
    }
}

// ---------------- s_logits = hid @ Wm2 + bm2 (warp per row) ----------------
__global__ __launch_bounds__(256) void k_mlp2(
    const float* __restrict__ hid, const float* __restrict__ Wm2,
    const float* __restrict__ bm2, float* __restrict__ out)
{
    __shared__ float ws[HID_ * KCL];
    for (int i = threadIdx.x; i < HID_ * KCL; i += 256) ws[i] = Wm2[i];
    __syncthreads();
    int warp = threadIdx.x >> 5, lane = threadIdx.x & 31;
    int row = blockIdx.x * 8 + warp;
    if (row >= N_NODES) return;
    float acc[KCL];
    #pragma unroll
    for (int k = 0; k < KCL; k++) acc[k] = 0.f;
    for (int c = lane; c < HID_; c += 32) {
        float v = hid[(size_t)row * HID_ + c];
        #pragma unroll
        for (int k = 0; k < KCL; k++) acc[k] = fmaf(v, ws[c * KCL + k], acc[k]);
    }
    #pragma unroll
    for (int k = 0; k < KCL; k++) {
        #pragma unroll
        for (int o = 16; o > 0; o >>= 1) acc[k] += __shfl_xor_sync(0xffffffffu, acc[k], o);
    }
    if (lane == 0) {
        #pragma unroll
        for (int k = 0; k < KCL; k++) out[(size_t)row * KCL + k] = acc[k] + bm2[k];
    }
}

// ---------------- softmax rows ----------------
__global__ void k_softmax(const float* __restrict__ logits) {
    int r = blockIdx.x * blockDim.x + threadIdx.x;
    if (r >= N_NODES) return;
    float v[KCL];
    float m = -1e30f;
    #pragma unroll
    for (int k = 0; k < KCL; k++) { v[k] = logits[r * KCL + k]; m = fmaxf(m, v[k]); }
    float sum = 0.f;
    #pragma unroll
    for (int k = 0; k < KCL; k++) { v[k] = expf(v[k] - m); sum += v[k]; }
    float inv = 1.f / sum;
    #pragma unroll
    for (int k = 0; k < KCL; k++) g_s[r * KCL + k] = v[k] * inv;
}

// ---------------- TV partials + distinct-edge count ----------------
__global__ __launch_bounds__(256) void k_tv(
    const int* __restrict__ src, const int* __restrict__ dst,
    const float* __restrict__ ew)
{
    __shared__ double sh[256];
    int e = blockIdx.x * 256 + threadIdx.x;   // grid covers E exactly
    int si = src[e], di = dst[e];
    float w = ew[e];
    float sum = 0.f;
    #pragma unroll
    for (int k = 0; k < KCL; k++) sum += fabsf(g_s[si * KCL + k] - g_s[di * KCL + k]);
    double val = (double)w * (double)sum;

    unsigned key = (unsigned)si * (unsigned)N_NODES + (unsigned)di;
    unsigned m = 1u << (key & 31u);
    unsigned old = atomicOr(&g_bitmap[key >> 5], m);
    int isnew = ((old & m) == 0u) ? 1 : 0;
    unsigned bal = __ballot_sync(0xffffffffu, isnew);
    if ((threadIdx.x & 31) == 0) atomicAdd(&g_nedges, __popc(bal));

    sh[threadIdx.x] = val;
    __syncthreads();
    for (int o = 128; o > 0; o >>= 1) {
        if (threadIdx.x < o) sh[threadIdx.x] += sh[threadIdx.x + o];
        __syncthreads();
    }
    if (threadIdx.x == 0) g_tv_part[blockIdx.x] = sh[0];
}

// ---------------- per-column order statistic (bitonic sort) ----------------
__global__ __launch_bounds__(1024) void k_quant() {
    __shared__ float a[N_NODES];
    int k = blockIdx.x;
    int tid = threadIdx.x;
    for (int i = tid; i < N_NODES; i += 1024) a[i] = g_s[i * KCL + k];
    __syncthreads();
    for (int size = 2; size <= N_NODES; size <<= 1) {
        for (int stride = size >> 1; stride > 0; stride >>= 1) {
            for (int i = tid; i < N_NODES; i += 1024) {
                int j = i ^ stride;
                if (j > i) {
                    bool up = ((i & size) == 0);
                    float x = a[i], y = a[j];
                    if ((x > y) == up) { a[i] = y; a[j] = x; }
                }
            }
            __syncthreads();
        }
    }
    // idx = N//K + 1 = 820 ; quant = sorted_ascending[N - idx] = [7372]
    if (tid == 0) g_quant[k] = a[N_NODES - (N_NODES / KCL + 1)];
}

// ---------------- balance asym partials ----------------
__global__ __launch_bounds__(256) void k_asym() {
    __shared__ double sh[256];
    int i = blockIdx.x * 256 + threadIdx.x;   // 320*256 = 81920 exactly
    float q = g_quant[i % KCL];
    float t = g_s[i] - q;
    double v = (t >= 0.f) ? (double)((KCL - 1) * t) : (double)(-t);
    sh[threadIdx.x] = v;
    __syncthreads();
    for (int o = 128; o > 0; o >>= 1) {
        if (threadIdx.x < o) sh[threadIdx.x] += sh[threadIdx.x + o];
        __syncthreads();
    }
    if (threadIdx.x == 0) g_asym_part[blockIdx.x] = sh[0];
}

// ---------------- finalize scalars ----------------
__global__ __launch_bounds__(1024) void k_final(float* __restrict__ out) {
    __shared__ double sh[1024];
    int tid = threadIdx.x;
    sh[tid] = g_tv_part[tid];
    __syncthreads();
    for (int o = 512; o > 0; o >>= 1) {
        if (tid < o) sh[tid] += sh[tid + o];
        __syncthreads();
    }
    double tvsum = sh[0];
    __syncthreads();
    sh[tid] = (tid < 320) ? g_asym_part[tid] : 0.0;
    __syncthreads();
    for (int o = 512; o > 0; o >>= 1) {
        if (tid < o) sh[tid] += sh[tid + o];
        __syncthreads();
    }
    if (tid == 0) {
        double asum = sh[0];
        double tv = tvsum / (2.0 * (double)g_nedges);
        double denom = (double)N_NODES * (double)(KCL - 1);
        double balv = (denom - asum) / denom;
        out[N_NODES * KCL + 0] = (float)((double)TV_COEFF * tv);
        out[N_NODES * KCL + 1] = (float)((double)BAL_COEFF * balv);
    }
}

// ---------------- launch ----------------
extern "C" void kernel_launch(void* const* d_in, const int* in_sizes, int n_in,
                              void* d_out, int out_size) {
    const float* x   = (const float*)d_in[0];
    const int*   ei  = (const int*)d_in[1];
    const float* ew  = (const float*)d_in[2];
    const float* W1  = (const float*)d_in[3];
    const float* b1  = (const float*)d_in[4];
    const float* W2  = (const float*)d_in[5];
    const float* b2  = (const float*)d_in[6];
    const float* Wm1 = (const float*)d_in[7];
    const float* bm1 = (const float*)d_in[8];
    const float* Wm2 = (const float*)d_in[9];
    const float* bm2 = (const float*)d_in[10];
    const int* src = ei;
    const int* dst = ei + E_EDGES;
    float* out = (float*)d_out;

    float *pA, *pB, *pHid;
    cudaGetSymbolAddress((void**)&pA,   g_bufA);
    cudaGetSymbolAddress((void**)&pB,   g_bufB);
    cudaGetSymbolAddress((void**)&pHid, g_hid);

    // clear bitmap/counters
    k_clear<<<(N_NODES * N_NODES / 32 + 1023) / 1024, 1024>>>();

    // CSR by dst
    k_hist<<<E_EDGES / 256, 256>>>(dst);
    k_scan<<<1, 1024>>>();
    k_scatter<<<E_EDGES / 256, 256>>>(dst);

    // layer 1: h = x @ W1 ; conv
    k_sgemm<<<dim3(MP_CH / 128, N_NODES / 128), 256>>>(x, W1, nullptr, pA, IN_CH_, MP_CH, 0);
    k_conv<<<N_NODES / 8, 256>>>(pA, b1, src, ew, pB);

    // layer 2: h = h1 @ W2 ; conv
    k_sgemm<<<dim3(MP_CH / 128, N_NODES / 128), 256>>>(pB, W2, nullptr, pA, MP_CH, MP_CH, 0);
    k_conv<<<N_NODES / 8, 256>>>(pA, b2, src, ew, pB);

    // MLP head
    k_sgemm<<<dim3(HID_ / 128, N_NODES / 128), 256>>>(pB, Wm1, bm1, pHid, MP_CH, HID_, 1);
    k_mlp2<<<N_NODES / 8, 256>>>(pHid, Wm2, bm2, out);

    // softmax, losses
    k_softmax<<<N_NODES / 256, 256>>>(out);
    k_tv<<<E_EDGES / 256, 256>>>(src, dst, ew);
    k_quant<<<KCL, 1024>>>();
    k_asym<<<(N_NODES * KCL) / 256, 256>>>();
    k_final<<<1, 1024>>>(out);
}